// round 1
// baseline (speedup 1.0000x reference)
#include <cuda_runtime.h>

// Stacked depth-3 tanh RNN, persistent-kernel wavefront implementation.
// B=16, T=2048, H=256, DEPTH=3 (shapes fixed by the problem).
//
// Grid: 96 CTAs = 3 layers x (2 batch-halves x 16 neuron-slices).
// Each CTA: 8 batches x 16 neurons, K = 512 (256 input + 256 recurrent).
// Weights live in registers (packed f32x2). Activations are exchanged
// through the output tensor itself (each (t,k) slot written exactly once),
// synchronized with one monotonic per-layer counter in global memory.

#define B_DIM 16
#define H_DIM 256
#define DEPTH 3
#define CTAS_PER_LAYER 32
#define NTHREADS 256

__device__ int g_cnt[DEPTH];

__device__ __forceinline__ int ld_acq(const int* p) {
    int v;
    asm volatile("ld.acquire.gpu.global.b32 %0, [%1];" : "=r"(v) : "l"(p) : "memory");
    return v;
}

__device__ __forceinline__ void red_add_release(int* p, int v) {
    asm volatile("red.release.gpu.global.add.s32 [%0], %1;" :: "l"(p), "r"(v) : "memory");
}

// packed fp32x2 fused multiply-add: d = a*b + d (lane-wise on the two fp32 halves)
__device__ __forceinline__ void ffma2(unsigned long long& d, unsigned long long a, unsigned long long b) {
    asm("fma.rn.f32x2 %0, %1, %2, %0;" : "+l"(d) : "l"(a), "l"(b));
}

__device__ __forceinline__ float lo32(unsigned long long v) { return __uint_as_float((unsigned)v); }
__device__ __forceinline__ float hi32(unsigned long long v) { return __uint_as_float((unsigned)(v >> 32)); }

__global__ void zero_cnt_kernel() {
    if (threadIdx.x < DEPTH) g_cnt[threadIdx.x] = 0;
}

__global__ void __launch_bounds__(NTHREADS, 1)
rnn_persistent_kernel(const float* __restrict__ x,
                      const int*   __restrict__ seq_lens,
                      const float* __restrict__ W_ih,
                      const float* __restrict__ W_hh,
                      const float* __restrict__ bias,
                      float* out,
                      int T) {
    __shared__ float in_s[8][512];   // 16 KB: [local batch][k]  (k<256: input, k>=256: h_prev)

    const int cta   = blockIdx.x;
    const int layer = cta >> 5;          // 0..2
    const int rr    = cta & 31;
    const int bh    = rr >> 4;           // 0..1  batch half  (batches bh*8 .. bh*8+7)
    const int ns    = rr & 15;           // 0..15 neuron slice (neurons ns*16 .. ns*16+15)

    const int tid  = threadIdx.x;
    const int w    = tid >> 5;
    const int lane = tid & 31;
    const int bg   = w >> 1;             // 0..3 -> local batches bg*2, bg*2+1
    const int ng   = w & 1;              // 0..1 -> neurons ng*8 .. ng*8+7 within slice

    const int n_base = ns * 16 + ng * 8; // global first neuron of this warp
    const int b_base = bh * 8 + bg * 2;  // global first batch of this warp

    // ---- preload weights into registers: Wr[i][j] = (W[n][k], W[n][k+1]) with
    //      n = n_base+i, k = 2*(32*j + lane). k<256 -> W_ih row, else W_hh row.
    unsigned long long Wr[8][8];
    {
        const float* wih = W_ih + layer * H_DIM * H_DIM;
        const float* whh = W_hh + layer * H_DIM * H_DIM;
#pragma unroll
        for (int i = 0; i < 8; i++) {
            const int n = n_base + i;
#pragma unroll
            for (int j = 0; j < 8; j++) {
                const int k2 = (j * 32 + lane) * 2;
                const float* src = (k2 < 256) ? (wih + n * 256 + k2)
                                              : (whh + n * 256 + (k2 - 256));
                Wr[i][j] = *(const unsigned long long*)src;
            }
        }
    }

    // ---- per-lane output assignment (lanes 0..15 of each warp own one (b,n) output)
    float bias_v = 0.0f;
    int   len_v  = 0;
    int   bidx   = 0;
    int   nr     = 0;
    if (lane < 16) {
        bidx   = b_base + (lane >> 3);
        nr     = n_base + (lane & 7);
        bias_v = bias[layer * H_DIM + nr];
        len_v  = seq_lens[bidx];
    }

    const int goal_per_step = CTAS_PER_LAYER;

    for (int t = 0; t < T; t++) {
        // ---- wait for inputs: upstream layer done with step t, own layer done with t-1
        if (tid == 0) {
            if (layer > 0) {
                const int goal = goal_per_step * (t + 1);
                while (ld_acq(&g_cnt[layer - 1]) < goal) { }
            }
            if (t > 0) {
                const int goal = goal_per_step * t;
                while (ld_acq(&g_cnt[layer]) < goal) { }
            }
        }
        __syncthreads();

        // ---- fill shared input [8][512]: lower 256 = layer input, upper 256 = h_prev
#pragma unroll
        for (int r4 = 0; r4 < 4; r4++) {
            const int q  = tid + r4 * 256;      // 0..1023 float4 slots
            const int bl = q >> 7;              // 0..7 local batch
            const int c  = (q & 127) << 2;      // 0..508
            const int bglob = bh * 8 + bl;
            float4 v;
            if (c < 256) {
                const float* p = (layer == 0)
                    ? (x   + ((bglob * T + t) * H_DIM) + c)
                    : (out + (((bglob * T + t) * DEPTH) + (layer - 1)) * H_DIM + c);
                v = *(const float4*)p;
            } else {
                if (t == 0) {
                    v = make_float4(0.f, 0.f, 0.f, 0.f);
                } else {
                    const float* p = out + (((bglob * T + (t - 1)) * DEPTH) + layer) * H_DIM + (c - 256);
                    v = *(const float4*)p;
                }
            }
            *(float4*)&in_s[bl][c] = v;
        }
        __syncthreads();

        // ---- compute: acc[b][n] = sum_k in[b][k] * W[n][k]  (k split across lanes)
        unsigned long long acc0[8], acc1[8];
#pragma unroll
        for (int i = 0; i < 8; i++) { acc0[i] = 0ull; acc1[i] = 0ull; }

        const unsigned long long* in0 = (const unsigned long long*)in_s[bg * 2 + 0];
        const unsigned long long* in1 = (const unsigned long long*)in_s[bg * 2 + 1];
#pragma unroll
        for (int j = 0; j < 8; j++) {
            const unsigned long long a0 = in0[j * 32 + lane];
            const unsigned long long a1 = in1[j * 32 + lane];
#pragma unroll
            for (int i = 0; i < 8; i++) {
                ffma2(acc0[i], a0, Wr[i][j]);
                ffma2(acc1[i], a1, Wr[i][j]);
            }
        }

        // ---- fold packed halves, butterfly-reduce over the 32 k-lanes
        float s[16];
#pragma unroll
        for (int i = 0; i < 8; i++) {
            s[i]     = lo32(acc0[i]) + hi32(acc0[i]);
            s[8 + i] = lo32(acc1[i]) + hi32(acc1[i]);
        }
#pragma unroll
        for (int off = 16; off; off >>= 1) {
#pragma unroll
            for (int m = 0; m < 16; m++) {
                s[m] += __shfl_xor_sync(0xffffffffu, s[m], off);
            }
        }

        // ---- activation + mask + publish
        if (lane < 16) {
            float v = tanhf(s[lane] + bias_v);
            if (t >= len_v) v = 0.0f;     // masked region: exact zeros (safe for downstream)
            out[(((bidx * T + t) * DEPTH) + layer) * H_DIM + nr] = v;
        }
        __threadfence();
        __syncthreads();
        if (tid == 0) red_add_release(&g_cnt[layer], 1);
    }
}

extern "C" void kernel_launch(void* const* d_in, const int* in_sizes, int n_in,
                              void* d_out, int out_size) {
    const float* x    = (const float*)d_in[0];
    const int*   seq  = (const int*)  d_in[1];
    const float* W_ih = (const float*)d_in[2];
    const float* W_hh = (const float*)d_in[3];
    const float* bias = (const float*)d_in[4];
    float* out = (float*)d_out;

    const int B = in_sizes[1];                    // 16
    const int T = in_sizes[0] / (B * H_DIM);      // 2048

    zero_cnt_kernel<<<1, 32>>>();
    rnn_persistent_kernel<<<DEPTH * CTAS_PER_LAYER, NTHREADS>>>(x, seq, W_ih, W_hh, bias, out, T);
}

// round 2
// speedup vs baseline: 1.6076x; 1.6076x over previous
#include <cuda_runtime.h>

// Stacked depth-3 tanh RNN, persistent wavefront with 4-CTA clusters.
// B=16, T=2048, H=256, DEPTH=3.
//
// Cluster (4 CTAs) = (layer, batch-pair p): batches 2p, 2p+1, all 256 neurons.
// CTA cid owns neurons [cid*64, cid*64+64). Recurrent h exchanged via DSMEM +
// one mbarrier phase per step. Cross-layer handoff stays in global memory
// (pipelined producer->consumer, per-(layer,pair) counter, cached poll).

#define H_DIM 256
#define DEPTH 3
#define NPAIRS 8
#define CLUSTER 4
#define NTHREADS 256

__device__ int g_cnt[DEPTH * NPAIRS];

__device__ __forceinline__ int ld_acq(const int* p) {
    int v;
    asm volatile("ld.acquire.gpu.global.b32 %0, [%1];" : "=r"(v) : "l"(p) : "memory");
    return v;
}
__device__ __forceinline__ void red_add_release(int* p, int v) {
    asm volatile("red.release.gpu.global.add.s32 [%0], %1;" :: "l"(p), "r"(v) : "memory");
}
__device__ __forceinline__ void ffma2(unsigned long long& d, unsigned long long a, unsigned long long b) {
    asm("fma.rn.f32x2 %0, %1, %2, %0;" : "+l"(d) : "l"(a), "l"(b));
}
__device__ __forceinline__ float lo32(unsigned long long v) { return __uint_as_float((unsigned)v); }
__device__ __forceinline__ float hi32(unsigned long long v) { return __uint_as_float((unsigned)(v >> 32)); }

__device__ __forceinline__ void mbar_wait(unsigned mb, int parity) {
    asm volatile(
        "{\n\t"
        ".reg .pred P;\n\t"
        "WL_%=:\n\t"
        "mbarrier.try_wait.parity.acquire.cluster.shared::cta.b64 P, [%0], %1, 0x989680;\n\t"
        "@P bra.uni WD_%=;\n\t"
        "bra.uni WL_%=;\n\t"
        "WD_%=:\n\t"
        "}" :: "r"(mb), "r"(parity) : "memory");
}

__device__ __forceinline__ void arrive_cluster(unsigned mb_local, int rank) {
    asm volatile(
        "{\n\t"
        ".reg .b32 ra;\n\t"
        "mapa.shared::cluster.u32 ra, %0, %1;\n\t"
        "mbarrier.arrive.release.cluster.shared::cluster.b64 _, [ra];\n\t"
        "}" :: "r"(mb_local), "r"(rank) : "memory");
}

__device__ __forceinline__ void st_cluster_b64(unsigned laddr, int rank, unsigned long long v) {
    asm volatile(
        "{\n\t"
        ".reg .b32 ra;\n\t"
        "mapa.shared::cluster.u32 ra, %0, %1;\n\t"
        "st.shared::cluster.b64 [ra], %2;\n\t"
        "}" :: "r"(laddr), "r"(rank), "l"(v) : "memory");
}

__global__ void zero_cnt_kernel() {
    if (threadIdx.x < DEPTH * NPAIRS) g_cnt[threadIdx.x] = 0;
}

__global__ void __launch_bounds__(NTHREADS, 1) __cluster_dims__(CLUSTER, 1, 1)
rnn_cluster_kernel(const float* __restrict__ x,
                   const int*   __restrict__ seq_lens,
                   const float* __restrict__ W_ih,
                   const float* __restrict__ W_hh,
                   const float* __restrict__ bias,
                   float* out,
                   int T) {
    __shared__ float in_s[2][256];              // [local batch][k<256]  layer input
    __shared__ float hbuf[2][2][256];           // [slot][local batch][n] recurrent h
    __shared__ __align__(8) unsigned long long mbar;

    const int bx    = blockIdx.x;
    const int cid   = bx & 3;                   // cluster rank (cluster dim x = 4)
    const int cl    = bx >> 2;                  // 0..23
    const int layer = cl >> 3;                  // 0..2
    const int p     = cl & 7;                   // batch pair: batches 2p, 2p+1

    const int tid  = threadIdx.x;
    const int w    = tid >> 5;                  // warp 0..7 -> neuron group
    const int lane = tid & 31;

    const int n_base = cid * 64 + w * 8;        // global neurons n_base..n_base+7

    const unsigned mb = (unsigned)__cvta_generic_to_shared(&mbar);

    // ---- init: mbarrier + zero hbuf, then cluster barrier
    if (tid == 0)
        asm volatile("mbarrier.init.shared.b64 [%0], %1;" :: "r"(mb), "r"(CLUSTER) : "memory");
    for (int i = tid; i < 2 * 2 * 256; i += NTHREADS) ((float*)hbuf)[i] = 0.0f;
    __syncthreads();
    asm volatile("barrier.cluster.arrive.aligned;" ::: "memory");
    asm volatile("barrier.cluster.wait.aligned;" ::: "memory");

    // ---- weights into registers: Wr[i][j] covers neuron n_base+i, k-pair j*32+lane
    //      j<4 -> W_ih (k2 = (j*32+lane)*2 < 256), j>=4 -> W_hh (k2-256)
    unsigned long long Wr[8][8];
    {
        const float* wih = W_ih + layer * H_DIM * H_DIM;
        const float* whh = W_hh + layer * H_DIM * H_DIM;
#pragma unroll
        for (int i = 0; i < 8; i++) {
            const int n = n_base + i;
#pragma unroll
            for (int j = 0; j < 8; j++) {
                const int k2 = (j * 32 + lane) * 2;
                const float* src = (k2 < 256) ? (wih + n * 256 + k2)
                                              : (whh + n * 256 + (k2 - 256));
                Wr[i][j] = *(const unsigned long long*)src;
            }
        }
    }

    // ---- per-lane output assignment (lanes 0..15 own one (b,n))
    float  bias_v = 0.0f;
    int    len_v  = 0;
    float* outp   = out;
    unsigned hoff = 0;                          // float index of own h slot (within one hbuf slot)
    if (lane < 16) {
        const int bl = lane >> 3;               // local batch 0/1
        const int nr = n_base + (lane & 7);
        const int bg = 2 * p + bl;
        bias_v = bias[layer * H_DIM + nr];
        len_v  = seq_lens[bg];
        outp   = out + (((size_t)bg * T) * DEPTH + layer) * H_DIM + nr;
        hoff   = bl * 256 + nr;
    }

    // ---- input LDG setup (threads 0..127 each load one float4 per step)
    const float* in_ptr = 0;
    int in_stride = 0, s_bl = 0, s_c4 = 0;
    if (tid < 128) {
        s_bl = tid >> 6;
        s_c4 = (tid & 63) << 2;
        const int bg = 2 * p + s_bl;
        if (layer == 0) {
            in_ptr = x + ((size_t)bg * T) * H_DIM + s_c4;
            in_stride = H_DIM;
        } else {
            in_ptr = out + (((size_t)bg * T) * DEPTH + (layer - 1)) * H_DIM + s_c4;
            in_stride = DEPTH * H_DIM;
        }
    }

    const int cnt_up = (layer > 0) ? ((layer - 1) * NPAIRS + p) : 0;
    const int cnt_dn = layer * NPAIRS + p;
    int seen = 0;

    for (int t = 0; t < T; t++) {
        // ---- upstream ready? (layer>0). Cached counter: zero L2 loads in steady state.
        if (layer > 0) {
            if (tid == 0) {
                const int goal = CLUSTER * (t + 1);
                while (seen < goal) seen = ld_acq(&g_cnt[cnt_up]);
            }
            __syncthreads();
        }

        // ---- issue input loads, then wait for h[t-1] exchange (LDG latency hides here)
        float4 inv = make_float4(0.f, 0.f, 0.f, 0.f);
        if (tid < 128) inv = *(const float4*)in_ptr;
        if (t > 0) mbar_wait(mb, (t - 1) & 1);
        if (tid < 128) {
            *(float4*)&in_s[s_bl][s_c4] = inv;
            in_ptr += in_stride;
        }
        __syncthreads();

        // ---- compute: acc[b][i] = sum_k a[b][k] * W[n_base+i][k], K split over 32 lanes
        const int ps = (t + 1) & 1;             // slot holding h[t-1]
        const unsigned long long* in0 = (const unsigned long long*)in_s[0];
        const unsigned long long* in1 = (const unsigned long long*)in_s[1];
        const unsigned long long* h0  = (const unsigned long long*)hbuf[ps][0];
        const unsigned long long* h1  = (const unsigned long long*)hbuf[ps][1];

        unsigned long long acc0[8], acc1[8];
#pragma unroll
        for (int i = 0; i < 8; i++) { acc0[i] = 0ull; acc1[i] = 0ull; }
#pragma unroll
        for (int j = 0; j < 4; j++) {
            const unsigned long long a0 = in0[j * 32 + lane];
            const unsigned long long a1 = in1[j * 32 + lane];
#pragma unroll
            for (int i = 0; i < 8; i++) { ffma2(acc0[i], a0, Wr[i][j]); ffma2(acc1[i], a1, Wr[i][j]); }
        }
#pragma unroll
        for (int j = 4; j < 8; j++) {
            const unsigned long long a0 = h0[(j - 4) * 32 + lane];
            const unsigned long long a1 = h1[(j - 4) * 32 + lane];
#pragma unroll
            for (int i = 0; i < 8; i++) { ffma2(acc0[i], a0, Wr[i][j]); ffma2(acc1[i], a1, Wr[i][j]); }
        }

        float s[16];
#pragma unroll
        for (int i = 0; i < 8; i++) {
            s[i]     = lo32(acc0[i]) + hi32(acc0[i]);
            s[8 + i] = lo32(acc1[i]) + hi32(acc1[i]);
        }
#pragma unroll
        for (int off = 16; off; off >>= 1) {
#pragma unroll
            for (int m = 0; m < 16; m++) s[m] += __shfl_xor_sync(0xffffffffu, s[m], off);
        }

        // ---- activation + mask; publish to global out and own hbuf slot
        const int cs = t & 1;
        if (lane < 16) {
            float v = tanhf(s[lane] + bias_v);
            if (t >= len_v) v = 0.0f;
            *outp = v;
            outp += DEPTH * H_DIM;
            ((float*)hbuf[cs])[hoff] = v;
        }
        __syncthreads();

        // ---- DSMEM scatter of own 64-neuron slice to the 3 peers + barrier arrives
        if (t < T - 1) {
            if (tid < 32) {
                const int sb = tid >> 4;        // local batch
                const int q  = tid & 15;        // 16B chunk within 64 neurons -> 2x b64
                const float* srcf = &hbuf[cs][sb][cid * 64 + q * 4];
                const unsigned long long v0 = ((const unsigned long long*)srcf)[0];
                const unsigned long long v1 = ((const unsigned long long*)srcf)[1];
                const unsigned laddr = (unsigned)__cvta_generic_to_shared(srcf);
#pragma unroll
                for (int r = 0; r < CLUSTER; r++) {
                    if (r == cid) continue;
                    st_cluster_b64(laddr, r, v0);
                    st_cluster_b64(laddr + 8, r, v1);
                }
            }
            __syncthreads();
            if (tid == 0) {
#pragma unroll
                for (int r = 0; r < CLUSTER; r++) arrive_cluster(mb, r);
            }
        }

        // ---- downstream flag (layers 0,1). STG out ordered by the syncthreads above.
        if (layer < 2 && tid == 0) red_add_release(&g_cnt[cnt_dn], 1);
    }
}

extern "C" void kernel_launch(void* const* d_in, const int* in_sizes, int n_in,
                              void* d_out, int out_size) {
    const float* x    = (const float*)d_in[0];
    const int*   seq  = (const int*)  d_in[1];
    const float* W_ih = (const float*)d_in[2];
    const float* W_hh = (const float*)d_in[3];
    const float* bias = (const float*)d_in[4];
    float* out = (float*)d_out;

    const int B = in_sizes[1];                    // 16
    const int T = in_sizes[0] / (B * H_DIM);      // 2048

    zero_cnt_kernel<<<1, 32>>>();
    rnn_cluster_kernel<<<DEPTH * NPAIRS * CLUSTER, NTHREADS>>>(x, seq, W_ih, W_hh, bias, out, T);
}

// round 9
// speedup vs baseline: 2.0530x; 1.2770x over previous
#include <cuda_runtime.h>

// Stacked depth-3 tanh RNN — single 12-CTA cluster per batch-pair, systolic
// lockstep. B=16, T=2048, H=256, DEPTH=3.
// Cluster (4,3,1): rank = cid + 4*layer. CTA owns 64 neurons x 2 batches.
// Iteration i: layer k computes t = i-k. One cluster-wide ping-pong mbarrier
// phase per iteration (immune to phase borrowing). All activation exchange is
// DSMEM pull; the only global traffic is read-only x (prefetched) and
// write-only out. No flags, no fences, no inter-cluster dependencies.

#define H_DIM 256
#define DEPTH 3
#define NTHREADS 256
#define CL_SZ 12

__device__ __forceinline__ void ffma2(unsigned long long& d, unsigned long long a, unsigned long long b) {
    asm("fma.rn.f32x2 %0, %1, %2, %0;" : "+l"(d) : "l"(a), "l"(b));
}
__device__ __forceinline__ float lo32(unsigned long long v) { return __uint_as_float((unsigned)v); }
__device__ __forceinline__ float hi32(unsigned long long v) { return __uint_as_float((unsigned)(v >> 32)); }

__device__ __forceinline__ unsigned smem_u32(const void* p) {
    return (unsigned)__cvta_generic_to_shared(p);
}
__device__ __forceinline__ unsigned mapa_addr(unsigned laddr, int rank) {
    unsigned ra;
    asm volatile("mapa.shared::cluster.u32 %0, %1, %2;" : "=r"(ra) : "r"(laddr), "r"(rank));
    return ra;
}
__device__ __forceinline__ void mbar_init(unsigned mb, int cnt) {
    asm volatile("mbarrier.init.shared.b64 [%0], %1;" :: "r"(mb), "r"(cnt) : "memory");
}
__device__ __forceinline__ void mbar_wait(unsigned mb, int parity) {
    asm volatile(
        "{\n\t"
        ".reg .pred P;\n\t"
        "WL_%=:\n\t"
        "mbarrier.try_wait.parity.acquire.cluster.shared::cta.b64 P, [%0], %1, 0x989680;\n\t"
        "@P bra.uni WD_%=;\n\t"
        "bra.uni WL_%=;\n\t"
        "WD_%=:\n\t"
        "}" :: "r"(mb), "r"(parity) : "memory");
}
__device__ __forceinline__ void arrive_mapped(unsigned addr) {
    asm volatile("mbarrier.arrive.release.cluster.shared::cluster.b64 _, [%0];"
                 :: "r"(addr) : "memory");
}
__device__ __forceinline__ unsigned long long ld_cl(unsigned addr) {
    unsigned long long v;
    asm volatile("ld.shared::cluster.b64 %0, [%1];" : "=l"(v) : "r"(addr) : "memory");
    return v;
}

__global__ void __launch_bounds__(NTHREADS, 1) __cluster_dims__(4, 3, 1)
rnn12_kernel(const float* __restrict__ x,
             const int*   __restrict__ seq_lens,
             const float* __restrict__ W_ih,
             const float* __restrict__ W_hh,
             const float* __restrict__ bias,
             float* out,
             int T) {
    __shared__ float in_s[3][2][256];           // layer-0 x ring (local, lock-free)
    __shared__ float hbuf[2][2][256];           // [slot t&1][local batch][n]; own 64-n slice
    __shared__ __align__(8) unsigned long long mbar[2];   // ping-pong lockstep barriers

    const int cid   = blockIdx.x & 3;           // rank within layer quad
    const int p     = blockIdx.x >> 2;          // batch pair: batches 2p, 2p+1
    const int layer = blockIdx.y;               // 0..2

    const int tid  = threadIdx.x;
    const int w    = tid >> 5;
    const int lane = tid & 31;
    const int n_base = cid * 64 + w * 8;

    const unsigned mb0 = smem_u32(&mbar[0]);
    const unsigned mb1 = smem_u32(&mbar[1]);
    if (tid == 0) { mbar_init(mb0, CL_SZ); mbar_init(mb1, CL_SZ); }
    for (int idx = tid; idx < 2 * 2 * 256; idx += NTHREADS) ((float*)hbuf)[idx] = 0.0f;
    __syncthreads();
    asm volatile("barrier.cluster.arrive.aligned;" ::: "memory");
    asm volatile("barrier.cluster.wait.aligned;" ::: "memory");

    // arrive targets (lanes 0..11 of warp 0 -> one rank each)
    unsigned ab0 = 0, ab1 = 0;
    if (tid < CL_SZ) { ab0 = mapa_addr(mb0, tid); ab1 = mapa_addr(mb1, tid); }

    // remote hbuf bases: own-layer quad (recurrent h), upstream quad (input)
    const unsigned hb = smem_u32(&hbuf[0][0][0]);
    unsigned own_rk[4], up_rk[4];
#pragma unroll
    for (int j = 0; j < 4; j++) {
        own_rk[j] = mapa_addr(hb, j + 4 * layer);
        up_rk[j]  = (layer > 0) ? mapa_addr(hb, j + 4 * (layer - 1)) : own_rk[j];
    }

    // ---- weights: Wr[i][j] = pair (W[n][k],W[n][k+1]), n=n_base+i, k=2*(j*32+lane)
    //      j<4 -> W_ih, j>=4 -> W_hh
    unsigned long long Wr[8][8];
    {
        const float* wih = W_ih + layer * H_DIM * H_DIM;
        const float* whh = W_hh + layer * H_DIM * H_DIM;
#pragma unroll
        for (int i = 0; i < 8; i++) {
            const int n = n_base + i;
#pragma unroll
            for (int j = 0; j < 8; j++) {
                const int k2 = (j * 32 + lane) * 2;
                const float* src = (k2 < 256) ? (wih + n * 256 + k2)
                                              : (whh + n * 256 + (k2 - 256));
                Wr[i][j] = *(const unsigned long long*)src;
            }
        }
    }

    // ---- writer lanes: even lanes. batch = lane>>4, neuron m = 4*b3+2*b2+b1.
    const bool active_lane = (lane & 1) == 0;
    float  bias_v = 0.0f;
    int    len_v  = -1;
    float* outp   = out;
    float* hp0 = 0; float* hp1 = 0;
    if (active_lane) {
        const int bl = lane >> 4;
        const int m  = ((lane >> 3) & 1) * 4 + ((lane >> 2) & 1) * 2 + ((lane >> 1) & 1);
        const int nr = n_base + m;
        const int bg = 2 * p + bl;
        bias_v = bias[layer * H_DIM + nr];
        len_v  = seq_lens[bg];
        outp   = out + (((size_t)bg * T) * DEPTH + layer) * H_DIM + nr;
        hp0 = &hbuf[0][bl][nr];
        hp1 = &hbuf[1][bl][nr];
    }

    // ---- layer-0 x loaders (tid<128): one float4 per step; x is read-only
    const bool loader = (layer == 0) && (tid < 128);
    const float* in_ptr = 0;
    int s_bl = 0, s_c4 = 0;
    if (loader) {
        s_bl = tid >> 6;
        s_c4 = (tid & 63) << 2;
        in_ptr = x + ((size_t)(2 * p + s_bl) * T) * H_DIM + s_c4;
        // prologue: t=0,1 into slots 0,1
        *(float4*)&in_s[0][s_bl][s_c4] = *(const float4*)in_ptr;
        *(float4*)&in_s[1][s_bl][s_c4] = *(const float4*)(in_ptr + H_DIM);
        in_ptr += 2 * H_DIM;
    }
    __syncthreads();

    for (int i = 0; i <= T + 1; i++) {
        const int t = i - layer;
        const bool active = (t >= 0) && (t < T);

        unsigned long long acc0[8], acc1[8];
#pragma unroll
        for (int q = 0; q < 8; q++) { acc0[q] = 0ull; acc1[q] = 0ull; }

        // ---- pre-wait work (purely local): x prefetch issue + layer-0 input FFMA
        float4 pf;
        const bool do_pf = loader && (i + 2 < T);
        if (do_pf) pf = *(const float4*)in_ptr;
        if (layer == 0 && active) {
            const unsigned long long* i0 = (const unsigned long long*)in_s[i % 3][0];
            const unsigned long long* i1 = (const unsigned long long*)in_s[i % 3][1];
#pragma unroll
            for (int j = 0; j < 4; j++) {
                const unsigned long long a0 = i0[j * 32 + lane];
                const unsigned long long a1 = i1[j * 32 + lane];
#pragma unroll
                for (int q = 0; q < 8; q++) { ffma2(acc0[q], a0, Wr[q][j]); ffma2(acc1[q], a1, Wr[q][j]); }
            }
        }

        // ---- lockstep wait for iteration i-1 (ping-pong: immune to phase borrow)
        if (i > 0) {
            const int sel = (i - 1) & 1;
            const int par = ((i - 1) >> 1) & 1;
            mbar_wait(sel ? mb1 : mb0, par);
        }

        if (active) {
            const unsigned po = (unsigned)((t + 1) & 1) * 2048u;   // own h[t-1] slot
            if (layer > 0) {
                const unsigned pi = (unsigned)(t & 1) * 2048u;     // upstream h[t] slot
#pragma unroll
                for (int j = 0; j < 4; j++) {
                    const unsigned o = 8u * (unsigned)(j * 32 + lane);
                    const unsigned long long iv0 = ld_cl(up_rk[j] + pi + o);
                    const unsigned long long iv1 = ld_cl(up_rk[j] + pi + o + 1024u);
                    const unsigned long long hv0 = ld_cl(own_rk[j] + po + o);
                    const unsigned long long hv1 = ld_cl(own_rk[j] + po + o + 1024u);
#pragma unroll
                    for (int q = 0; q < 8; q++) {
                        ffma2(acc0[q], iv0, Wr[q][j]);     ffma2(acc1[q], iv1, Wr[q][j]);
                        ffma2(acc0[q], hv0, Wr[q][j + 4]); ffma2(acc1[q], hv1, Wr[q][j + 4]);
                    }
                }
            } else {
#pragma unroll
                for (int j = 0; j < 4; j++) {
                    const unsigned o = 8u * (unsigned)(j * 32 + lane);
                    const unsigned long long hv0 = ld_cl(own_rk[j] + po + o);
                    const unsigned long long hv1 = ld_cl(own_rk[j] + po + o + 1024u);
#pragma unroll
                    for (int q = 0; q < 8; q++) { ffma2(acc0[q], hv0, Wr[q][j + 4]); ffma2(acc1[q], hv1, Wr[q][j + 4]); }
                }
            }

            // ---- folded tree reduction: 16 shfl, all static register indexing
            float k[8];
            {
                float s0[8], s1[8];
#pragma unroll
                for (int q = 0; q < 8; q++) {
                    s0[q] = lo32(acc0[q]) + hi32(acc0[q]);
                    s1[q] = lo32(acc1[q]) + hi32(acc1[q]);
                }
                const bool b4 = (lane & 16) != 0;
#pragma unroll
                for (int m = 0; m < 8; m++) {
                    const float a = b4 ? s1[m] : s0[m];
                    const float b = b4 ? s0[m] : s1[m];
                    k[m] = a + __shfl_xor_sync(0xffffffffu, b, 16);
                }
            }
            {
                const bool b3 = (lane & 8) != 0;
#pragma unroll
                for (int q = 0; q < 4; q++) {
                    const float a = b3 ? k[q + 4] : k[q];
                    const float b = b3 ? k[q] : k[q + 4];
                    k[q] = a + __shfl_xor_sync(0xffffffffu, b, 8);
                }
            }
            {
                const bool b2 = (lane & 4) != 0;
#pragma unroll
                for (int q = 0; q < 2; q++) {
                    const float a = b2 ? k[q + 2] : k[q];
                    const float b = b2 ? k[q] : k[q + 2];
                    k[q] = a + __shfl_xor_sync(0xffffffffu, b, 4);
                }
            }
            {
                const bool b1 = (lane & 2) != 0;
                const float a = b1 ? k[1] : k[0];
                const float b = b1 ? k[0] : k[1];
                k[0] = a + __shfl_xor_sync(0xffffffffu, b, 2);
            }
            k[0] += __shfl_xor_sync(0xffffffffu, k[0], 1);

            // ---- activation + mask; STG out (write-only) + local STS of own slice
            if (active_lane) {
                float v = tanhf(k[0] + bias_v);
                if (t >= len_v) v = 0.0f;
                *outp = v;
                outp += DEPTH * H_DIM;
                *(((t & 1) ? hp1 : hp0)) = v;
            }
        }

        // ---- commit x prefetch for t+2 (slot reuse protected by last bar.sync)
        if (do_pf) {
            *(float4*)&in_s[(i + 2) % 3][s_bl][s_c4] = pf;
            in_ptr += H_DIM;
        }

        __syncthreads();                        // STS drained; all iteration-i reads done
        if (i <= T && tid < CL_SZ) {
            arrive_mapped((i & 1) ? ab1 : ab0); // release-arrive to rank 'tid'
        }
    }

    // terminal: no CTA exits while peers may still pull/arrive into it
    asm volatile("barrier.cluster.arrive.aligned;" ::: "memory");
    asm volatile("barrier.cluster.wait.aligned;" ::: "memory");
}

extern "C" void kernel_launch(void* const* d_in, const int* in_sizes, int n_in,
                              void* d_out, int out_size) {
    const float* x    = (const float*)d_in[0];
    const int*   seq  = (const int*)  d_in[1];
    const float* W_ih = (const float*)d_in[2];
    const float* W_hh = (const float*)d_in[3];
    const float* bias = (const float*)d_in[4];
    float* out = (float*)d_out;

    const int B = in_sizes[1];                    // 16
    const int T = in_sizes[0] / (B * H_DIM);      // 2048

    // 12-CTA clusters need the non-portable size opt-in (idempotent host call).
    cudaFuncSetAttribute(rnn12_kernel,
                         cudaFuncAttributeNonPortableClusterSizeAllowed, 1);

    rnn12_kernel<<<dim3((B / 2) * 4, DEPTH, 1), NTHREADS>>>(x, seq, W_ih, W_hh, bias, out, T);
}

// round 10
// speedup vs baseline: 2.1898x; 1.0667x over previous
#include <cuda_runtime.h>

// Stacked depth-3 tanh RNN — single 12-CTA cluster per batch-pair, systolic
// lockstep. B=16, T=2048, H=256, DEPTH=3.
// Cluster (4,3,1): rank = cid + 4*layer. CTA owns 64 neurons x 2 batches.
// Iteration i: layer k computes t = i-k. One ping-pong mbarrier phase per
// iteration (immune to phase borrowing). R10: all remote pulls batch-issued
// post-wait (MLP=14); own-chunk h FFMA moved pre-wait via cid-permuted
// W_hh register layout (slot 4 == own chunk, always local SMEM).

#define H_DIM 256
#define DEPTH 3
#define NTHREADS 256
#define CL_SZ 12

typedef unsigned long long ull;

__device__ __forceinline__ void ffma2(ull& d, ull a, ull b) {
    asm("fma.rn.f32x2 %0, %1, %2, %0;" : "+l"(d) : "l"(a), "l"(b));
}
__device__ __forceinline__ float lo32(ull v) { return __uint_as_float((unsigned)v); }
__device__ __forceinline__ float hi32(ull v) { return __uint_as_float((unsigned)(v >> 32)); }

__device__ __forceinline__ unsigned smem_u32(const void* p) {
    return (unsigned)__cvta_generic_to_shared(p);
}
__device__ __forceinline__ unsigned mapa_addr(unsigned laddr, int rank) {
    unsigned ra;
    asm volatile("mapa.shared::cluster.u32 %0, %1, %2;" : "=r"(ra) : "r"(laddr), "r"(rank));
    return ra;
}
__device__ __forceinline__ void mbar_init(unsigned mb, int cnt) {
    asm volatile("mbarrier.init.shared.b64 [%0], %1;" :: "r"(mb), "r"(cnt) : "memory");
}
__device__ __forceinline__ void mbar_wait(unsigned mb, int parity) {
    asm volatile(
        "{\n\t"
        ".reg .pred P;\n\t"
        "WL_%=:\n\t"
        "mbarrier.try_wait.parity.acquire.cluster.shared::cta.b64 P, [%0], %1, 0x989680;\n\t"
        "@P bra.uni WD_%=;\n\t"
        "bra.uni WL_%=;\n\t"
        "WD_%=:\n\t"
        "}" :: "r"(mb), "r"(parity) : "memory");
}
__device__ __forceinline__ void arrive_mapped(unsigned addr) {
    asm volatile("mbarrier.arrive.release.cluster.shared::cluster.b64 _, [%0];"
                 :: "r"(addr) : "memory");
}
__device__ __forceinline__ ull ld_cl(unsigned addr) {
    ull v;
    asm volatile("ld.shared::cluster.b64 %0, [%1];" : "=l"(v) : "r"(addr) : "memory");
    return v;
}

__global__ void __launch_bounds__(NTHREADS, 1) __cluster_dims__(4, 3, 1)
rnn12_kernel(const float* __restrict__ x,
             const int*   __restrict__ seq_lens,
             const float* __restrict__ W_ih,
             const float* __restrict__ W_hh,
             const float* __restrict__ bias,
             float* out,
             int T) {
    __shared__ float in_s[3][2][256];           // layer-0 x ring (local, lock-free)
    __shared__ float hbuf[2][2][256];           // [slot t&1][local batch][n]; own slice
    __shared__ __align__(8) ull mbar[2];        // ping-pong lockstep barriers

    const int cid   = blockIdx.x & 3;           // rank within layer quad
    const int p     = blockIdx.x >> 2;          // batch pair: batches 2p, 2p+1
    const int layer = blockIdx.y;               // 0..2

    const int tid  = threadIdx.x;
    const int w    = tid >> 5;
    const int lane = tid & 31;
    const int n_base = cid * 64 + w * 8;

    const unsigned mb0 = smem_u32(&mbar[0]);
    const unsigned mb1 = smem_u32(&mbar[1]);
    if (tid == 0) { mbar_init(mb0, CL_SZ); mbar_init(mb1, CL_SZ); }
    for (int idx = tid; idx < 2 * 2 * 256; idx += NTHREADS) ((float*)hbuf)[idx] = 0.0f;
    __syncthreads();
    asm volatile("barrier.cluster.arrive.aligned;" ::: "memory");
    asm volatile("barrier.cluster.wait.aligned;" ::: "memory");

    // arrive targets (lanes 0..11 of warp 0 -> one rank each)
    unsigned ab0 = 0, ab1 = 0;
    if (tid < CL_SZ) { ab0 = mapa_addr(mb0, tid); ab1 = mapa_addr(mb1, tid); }

    // pull addresses (loop-invariant; add parity offset per step)
    const unsigned hb = smem_u32(&hbuf[0][0][0]);
    unsigned up_adr[4];                         // upstream input chunks j=0..3
    unsigned hadr[3];                           // own-layer peer h chunks jj=1..3
#pragma unroll
    for (int j = 0; j < 4; j++) {
        const unsigned rk = mapa_addr(hb, j + 4 * ((layer > 0) ? layer - 1 : 0));
        up_adr[j] = rk + 8u * (unsigned)(j * 32 + lane);
    }
#pragma unroll
    for (int jj = 1; jj < 4; jj++) {
        const int c = (cid + jj) & 3;
        hadr[jj - 1] = mapa_addr(hb, c + 4 * layer) + 8u * (unsigned)(c * 32 + lane);
    }
    // own chunk (jj=0): local SMEM, ull index
    const ull* hloc = (const ull*)hbuf + (cid * 32 + lane);
    // strides in ull units: slot = 256, batch = 128

    // ---- weights: input chunks j=0..3 in slots 0..3 (k2=2*(j*32+lane));
    //      h chunks permuted by cid: slot 4+jj holds phys chunk c=(cid+jj)&3,
    //      so the own (local) chunk is ALWAYS slot 4 (static reg indexing).
    ull Wr[8][8];
    {
        const float* wih = W_ih + layer * H_DIM * H_DIM;
        const float* whh = W_hh + layer * H_DIM * H_DIM;
#pragma unroll
        for (int i = 0; i < 8; i++) {
            const int n = n_base + i;
#pragma unroll
            for (int j = 0; j < 4; j++)
                Wr[i][j] = *(const ull*)(wih + n * 256 + (j * 32 + lane) * 2);
#pragma unroll
            for (int jj = 0; jj < 4; jj++) {
                const int c = (cid + jj) & 3;
                Wr[i][4 + jj] = *(const ull*)(whh + n * 256 + (c * 32 + lane) * 2);
            }
        }
    }

    // ---- writer lanes: even lanes. batch = lane>>4, neuron m = 4*b3+2*b2+b1.
    const bool active_lane = (lane & 1) == 0;
    float  bias_v = 0.0f;
    int    len_v  = -1;
    float* outp   = out;
    float* hp0 = 0; float* hp1 = 0;
    if (active_lane) {
        const int bl = lane >> 4;
        const int m  = ((lane >> 3) & 1) * 4 + ((lane >> 2) & 1) * 2 + ((lane >> 1) & 1);
        const int nr = n_base + m;
        const int bg = 2 * p + bl;
        bias_v = bias[layer * H_DIM + nr];
        len_v  = seq_lens[bg];
        outp   = out + (((size_t)bg * T) * DEPTH + layer) * H_DIM + nr;
        hp0 = &hbuf[0][bl][nr];
        hp1 = &hbuf[1][bl][nr];
    }

    // ---- layer-0 x loaders (tid<128): one float4 per step; x is read-only
    const bool loader = (layer == 0) && (tid < 128);
    const float* in_ptr = 0;
    int s_bl = 0, s_c4 = 0;
    if (loader) {
        s_bl = tid >> 6;
        s_c4 = (tid & 63) << 2;
        in_ptr = x + ((size_t)(2 * p + s_bl) * T) * H_DIM + s_c4;
        *(float4*)&in_s[0][s_bl][s_c4] = *(const float4*)in_ptr;
        *(float4*)&in_s[1][s_bl][s_c4] = *(const float4*)(in_ptr + H_DIM);
        in_ptr += 2 * H_DIM;
    }
    __syncthreads();

    for (int i = 0; i <= T + 1; i++) {
        const int t = i - layer;
        const bool active = (t >= 0) && (t < T);
        const int ps = (t + 1) & 1;             // slot holding h[t-1]

        ull acc0[8], acc1[8];
#pragma unroll
        for (int q = 0; q < 8; q++) { acc0[q] = 0ull; acc1[q] = 0ull; }

        // ---- pre-wait work (all local): x prefetch, layer-0 input FFMA,
        //      own-chunk h FFMA (own slice is local SMEM, ordered by prev bar.sync)
        float4 pf;
        const bool do_pf = loader && (i + 2 < T);
        if (do_pf) pf = *(const float4*)in_ptr;
        if (active) {
            const ull o0 = hloc[ps * 256];
            const ull o1 = hloc[ps * 256 + 128];
#pragma unroll
            for (int q = 0; q < 8; q++) { ffma2(acc0[q], o0, Wr[q][4]); ffma2(acc1[q], o1, Wr[q][4]); }
            if (layer == 0) {
                const ull* i0 = (const ull*)in_s[i % 3][0];
                const ull* i1 = (const ull*)in_s[i % 3][1];
#pragma unroll
                for (int j = 0; j < 4; j++) {
                    const ull a0 = i0[j * 32 + lane];
                    const ull a1 = i1[j * 32 + lane];
#pragma unroll
                    for (int q = 0; q < 8; q++) { ffma2(acc0[q], a0, Wr[q][j]); ffma2(acc1[q], a1, Wr[q][j]); }
                }
            }
        }

        // ---- lockstep wait for iteration i-1 (ping-pong: immune to phase borrow)
        if (i > 0) {
            const int sel = (i - 1) & 1;
            const int par = ((i - 1) >> 1) & 1;
            mbar_wait(sel ? mb1 : mb0, par);
        }

        if (active) {
            const unsigned po = (unsigned)ps * 2048u;      // own-layer h[t-1] slot
            // ---- batch-issue ALL remote pulls (one latency exposure, MLP<=14)
            ull hv0[3], hv1[3], iv0[4], iv1[4];
#pragma unroll
            for (int jj = 0; jj < 3; jj++) {
                hv0[jj] = ld_cl(hadr[jj] + po);
                hv1[jj] = ld_cl(hadr[jj] + po + 1024u);
            }
            if (layer > 0) {
                const unsigned pi = (unsigned)(t & 1) * 2048u;  // upstream h[t] slot
#pragma unroll
                for (int j = 0; j < 4; j++) {
                    iv0[j] = ld_cl(up_adr[j] + pi);
                    iv1[j] = ld_cl(up_adr[j] + pi + 1024u);
                }
#pragma unroll
                for (int j = 0; j < 4; j++)
#pragma unroll
                    for (int q = 0; q < 8; q++) { ffma2(acc0[q], iv0[j], Wr[q][j]); ffma2(acc1[q], iv1[j], Wr[q][j]); }
            }
#pragma unroll
            for (int jj = 0; jj < 3; jj++)
#pragma unroll
                for (int q = 0; q < 8; q++) { ffma2(acc0[q], hv0[jj], Wr[q][5 + jj]); ffma2(acc1[q], hv1[jj], Wr[q][5 + jj]); }

            // ---- folded tree reduction: 16 shfl, all static register indexing
            float k[8];
            {
                float s0[8], s1[8];
#pragma unroll
                for (int q = 0; q < 8; q++) {
                    s0[q] = lo32(acc0[q]) + hi32(acc0[q]);
                    s1[q] = lo32(acc1[q]) + hi32(acc1[q]);
                }
                const bool b4 = (lane & 16) != 0;
#pragma unroll
                for (int m = 0; m < 8; m++) {
                    const float a = b4 ? s1[m] : s0[m];
                    const float b = b4 ? s0[m] : s1[m];
                    k[m] = a + __shfl_xor_sync(0xffffffffu, b, 16);
                }
            }
            {
                const bool b3 = (lane & 8) != 0;
#pragma unroll
                for (int q = 0; q < 4; q++) {
                    const float a = b3 ? k[q + 4] : k[q];
                    const float b = b3 ? k[q] : k[q + 4];
                    k[q] = a + __shfl_xor_sync(0xffffffffu, b, 8);
                }
            }
            {
                const bool b2 = (lane & 4) != 0;
#pragma unroll
                for (int q = 0; q < 2; q++) {
                    const float a = b2 ? k[q + 2] : k[q];
                    const float b = b2 ? k[q] : k[q + 2];
                    k[q] = a + __shfl_xor_sync(0xffffffffu, b, 4);
                }
            }
            {
                const bool b1 = (lane & 2) != 0;
                const float a = b1 ? k[1] : k[0];
                const float b = b1 ? k[0] : k[1];
                k[0] = a + __shfl_xor_sync(0xffffffffu, b, 2);
            }
            k[0] += __shfl_xor_sync(0xffffffffu, k[0], 1);

            // ---- activation + mask; STG out (write-only) + local STS of own slice
            if (active_lane) {
                float v = tanhf(k[0] + bias_v);
                if (t >= len_v) v = 0.0f;
                *outp = v;
                outp += DEPTH * H_DIM;
                *(((t & 1) ? hp1 : hp0)) = v;
            }
        }

        // ---- commit x prefetch for t+2 (slot reuse protected by barrier chain)
        if (do_pf) {
            *(float4*)&in_s[(i + 2) % 3][s_bl][s_c4] = pf;
            in_ptr += H_DIM;
        }

        __syncthreads();                        // STS drained; all iteration-i reads done
        if (i <= T && tid < CL_SZ) {
            arrive_mapped((i & 1) ? ab1 : ab0); // release-arrive to rank 'tid'
        }
    }

    // terminal: no CTA exits while peers may still pull/arrive into it
    asm volatile("barrier.cluster.arrive.aligned;" ::: "memory");
    asm volatile("barrier.cluster.wait.aligned;" ::: "memory");
}

extern "C" void kernel_launch(void* const* d_in, const int* in_sizes, int n_in,
                              void* d_out, int out_size) {
    const float* x    = (const float*)d_in[0];
    const int*   seq  = (const int*)  d_in[1];
    const float* W_ih = (const float*)d_in[2];
    const float* W_hh = (const float*)d_in[3];
    const float* bias = (const float*)d_in[4];
    float* out = (float*)d_out;

    const int B = in_sizes[1];                    // 16
    const int T = in_sizes[0] / (B * H_DIM);      // 2048

    cudaFuncSetAttribute(rnn12_kernel,
                         cudaFuncAttributeNonPortableClusterSizeAllowed, 1);

    rnn12_kernel<<<dim3((B / 2) * 4, DEPTH, 1), NTHREADS>>>(x, seq, W_ih, W_hh, bias, out, T);
}

// round 13
// speedup vs baseline: 2.2093x; 1.0089x over previous
#include <cuda_runtime.h>

// Stacked depth-3 tanh RNN — single 12-CTA cluster per batch-pair, systolic
// lockstep, PULL-based exchange. B=16, T=2048, H=256, DEPTH=3.
// Cluster (4,3,1): rank = cid + 4*layer. Iteration i: layer k computes t=i-k.
// Ping-pong mbarriers (phase-borrow immune). Fast MUFU tanh. Loader LDG is
// issued one iteration before its STS commit — R13 fixes the R11/R12 pointer
// bug (advance in_ptr at ISSUE, not at commit).

#define H_DIM 256
#define DEPTH 3
#define NTHREADS 256
#define CL_SZ 12

typedef unsigned long long ull;

__device__ __forceinline__ void ffma2(ull& d, ull a, ull b) {
    asm("fma.rn.f32x2 %0, %1, %2, %0;" : "+l"(d) : "l"(a), "l"(b));
}
__device__ __forceinline__ float lo32(ull v) { return __uint_as_float((unsigned)v); }
__device__ __forceinline__ float hi32(ull v) { return __uint_as_float((unsigned)(v >> 32)); }

__device__ __forceinline__ unsigned smem_u32(const void* p) {
    return (unsigned)__cvta_generic_to_shared(p);
}
__device__ __forceinline__ unsigned mapa_addr(unsigned laddr, int rank) {
    unsigned ra;
    asm volatile("mapa.shared::cluster.u32 %0, %1, %2;" : "=r"(ra) : "r"(laddr), "r"(rank));
    return ra;
}
__device__ __forceinline__ void mbar_init(unsigned mb, int cnt) {
    asm volatile("mbarrier.init.shared.b64 [%0], %1;" :: "r"(mb), "r"(cnt) : "memory");
}
__device__ __forceinline__ void mbar_wait(unsigned mb, int parity) {
    asm volatile(
        "{\n\t"
        ".reg .pred P;\n\t"
        "WL_%=:\n\t"
        "mbarrier.try_wait.parity.acquire.cluster.shared::cta.b64 P, [%0], %1, 0x989680;\n\t"
        "@P bra.uni WD_%=;\n\t"
        "bra.uni WL_%=;\n\t"
        "WD_%=:\n\t"
        "}" :: "r"(mb), "r"(parity) : "memory");
}
__device__ __forceinline__ void arrive_mapped(unsigned addr) {
    asm volatile("mbarrier.arrive.release.cluster.shared::cluster.b64 _, [%0];"
                 :: "r"(addr) : "memory");
}
__device__ __forceinline__ ull ld_cl(unsigned addr) {
    ull v;
    asm volatile("ld.shared::cluster.b64 %0, [%1];" : "=l"(v) : "r"(addr) : "memory");
    return v;
}
// fast tanh: tanh(z) = 1 - 2/(exp(2z)+1) via MUFU ex2/rcp (~60 cyc vs ~200
// for libdevice tanhf). Numerical adequacy proven by the R4/R5 bit-identical
// error experiment (error unchanged when swapping tanhf <-> this).
__device__ __forceinline__ float fast_tanh(float z) {
    const float e = __expf(z + z);
    return 1.0f - __fdividef(2.0f, e + 1.0f);
}

__global__ void __launch_bounds__(NTHREADS, 1) __cluster_dims__(4, 3, 1)
rnn12_kernel(const float* __restrict__ x,
             const int*   __restrict__ seq_lens,
             const float* __restrict__ W_ih,
             const float* __restrict__ W_hh,
             const float* __restrict__ bias,
             float* out,
             int T) {
    __shared__ float in_s[3][2][256];           // layer-0 x ring (local)
    __shared__ float hbuf[2][2][256];           // [slot t&1][local batch][n]; own slice
    __shared__ __align__(8) ull mbar[2];        // ping-pong lockstep barriers

    const int cid   = blockIdx.x & 3;           // rank within layer quad
    const int p     = blockIdx.x >> 2;          // batch pair: batches 2p, 2p+1
    const int layer = blockIdx.y;               // 0..2

    const int tid  = threadIdx.x;
    const int w    = tid >> 5;
    const int lane = tid & 31;
    const int n_base = cid * 64 + w * 8;

    const unsigned mb0 = smem_u32(&mbar[0]);
    const unsigned mb1 = smem_u32(&mbar[1]);
    if (tid == 0) { mbar_init(mb0, CL_SZ); mbar_init(mb1, CL_SZ); }
    for (int idx = tid; idx < 2 * 2 * 256; idx += NTHREADS) ((float*)hbuf)[idx] = 0.0f;
    __syncthreads();
    asm volatile("barrier.cluster.arrive.aligned;" ::: "memory");
    asm volatile("barrier.cluster.wait.aligned;" ::: "memory");

    // arrive targets (lanes 0..11 of warp 0 -> one rank each)
    unsigned ab0 = 0, ab1 = 0;
    if (tid < CL_SZ) { ab0 = mapa_addr(mb0, tid); ab1 = mapa_addr(mb1, tid); }

    // pull addresses (loop-invariant; add parity offset per step)
    const unsigned hb = smem_u32(&hbuf[0][0][0]);
    unsigned up_adr[4];                         // upstream input chunks j=0..3
    unsigned hadr[3];                           // own-layer peer h chunks jj=1..3
#pragma unroll
    for (int j = 0; j < 4; j++) {
        const unsigned rk = mapa_addr(hb, j + 4 * ((layer > 0) ? layer - 1 : 0));
        up_adr[j] = rk + 8u * (unsigned)(j * 32 + lane);
    }
#pragma unroll
    for (int jj = 1; jj < 4; jj++) {
        const int c = (cid + jj) & 3;
        hadr[jj - 1] = mapa_addr(hb, c + 4 * layer) + 8u * (unsigned)(c * 32 + lane);
    }
    // own chunk (jj=0): local SMEM, ull index (slot stride 256, batch stride 128)
    const ull* hloc = (const ull*)hbuf + (cid * 32 + lane);

    // ---- weights: input chunks j=0..3 in slots 0..3 (k2=2*(j*32+lane));
    //      h chunks permuted by cid: slot 4+jj holds phys chunk c=(cid+jj)&3,
    //      so the own (local) chunk is ALWAYS slot 4 (static reg indexing).
    ull Wr[8][8];
    {
        const float* wih = W_ih + layer * H_DIM * H_DIM;
        const float* whh = W_hh + layer * H_DIM * H_DIM;
#pragma unroll
        for (int i = 0; i < 8; i++) {
            const int n = n_base + i;
#pragma unroll
            for (int j = 0; j < 4; j++)
                Wr[i][j] = *(const ull*)(wih + n * 256 + (j * 32 + lane) * 2);
#pragma unroll
            for (int jj = 0; jj < 4; jj++) {
                const int c = (cid + jj) & 3;
                Wr[i][4 + jj] = *(const ull*)(whh + n * 256 + (c * 32 + lane) * 2);
            }
        }
    }

    // ---- writer lanes: even lanes. batch = lane>>4, neuron m = 4*b3+2*b2+b1.
    const bool active_lane = (lane & 1) == 0;
    float  bias_v = 0.0f;
    int    len_v  = -1;
    float* outp   = out;
    float* hp0 = 0; float* hp1 = 0;
    if (active_lane) {
        const int bl = lane >> 4;
        const int m  = ((lane >> 3) & 1) * 4 + ((lane >> 2) & 1) * 2 + ((lane >> 1) & 1);
        const int nr = n_base + m;
        const int bg = 2 * p + bl;
        bias_v = bias[layer * H_DIM + nr];
        len_v  = seq_lens[bg];
        outp   = out + (((size_t)bg * T) * DEPTH + layer) * H_DIM + nr;
        hp0 = &hbuf[0][bl][nr];
        hp1 = &hbuf[1][bl][nr];
    }

    // ---- layer-0 x loaders (tid<128): LDG issued 1 iteration before commit.
    //      in_ptr advances at ISSUE time (R13 fix for the R11/R12 off-by-one).
    const bool loader = (layer == 0) && (tid < 128);
    const float* in_ptr = 0;
    int s_bl = 0, s_c4 = 0;
    if (loader) {
        s_bl = tid >> 6;
        s_c4 = (tid & 63) << 2;
        in_ptr = x + ((size_t)(2 * p + s_bl) * T) * H_DIM + s_c4;
        *(float4*)&in_s[0][s_bl][s_c4] = *(const float4*)in_ptr;           // t=0
        *(float4*)&in_s[1][s_bl][s_c4] = *(const float4*)(in_ptr + H_DIM); // t=1
        in_ptr += 2 * H_DIM;                    // -> x[2]
    }
    float4 pf_cur = make_float4(0.f, 0.f, 0.f, 0.f);
    __syncthreads();

    for (int i = 0; i <= T + 1; i++) {
        const int t = i - layer;
        const bool active = (t >= 0) && (t < T);
        const int ps = (t + 1) & 1;             // slot holding h[t-1]

        ull acc0[8], acc1[8];
#pragma unroll
        for (int q = 0; q < 8; q++) { acc0[q] = 0ull; acc1[q] = 0ull; }

        // ---- pre-wait (all local): issue x[i+2] LDG (commits at i+1, read i+2);
        //      own-chunk h FFMA, layer-0 input FFMA
        float4 pf_next;
        const bool do_issue = loader && (i + 2 < T);
        if (do_issue) {
            pf_next = *(const float4*)in_ptr;   // x[i+2]
            in_ptr += H_DIM;                    // advance at ISSUE (the fix)
        }

        if (active) {
            const ull o0 = hloc[ps * 256];
            const ull o1 = hloc[ps * 256 + 128];
#pragma unroll
            for (int q = 0; q < 8; q++) { ffma2(acc0[q], o0, Wr[q][4]); ffma2(acc1[q], o1, Wr[q][4]); }
            if (layer == 0) {
                const ull* i0 = (const ull*)in_s[i % 3][0];
                const ull* i1 = (const ull*)in_s[i % 3][1];
#pragma unroll
                for (int j = 0; j < 4; j++) {
                    const ull a0 = i0[j * 32 + lane];
                    const ull a1 = i1[j * 32 + lane];
#pragma unroll
                    for (int q = 0; q < 8; q++) { ffma2(acc0[q], a0, Wr[q][j]); ffma2(acc1[q], a1, Wr[q][j]); }
                }
            }
        }

        // ---- lockstep wait for iteration i-1 (ping-pong, phase-borrow immune)
        if (i > 0) {
            const int sel = (i - 1) & 1;
            const int par = ((i - 1) >> 1) & 1;
            mbar_wait(sel ? mb1 : mb0, par);
        }

        // ---- commit x[i+1] (issued LAST iteration) into slot (i+1)%3
        if (loader && i >= 1 && i + 1 < T) {
            *(float4*)&in_s[(i + 1) % 3][s_bl][s_c4] = pf_cur;
        }
        if (do_issue) pf_cur = pf_next;

        if (active) {
            const unsigned po = (unsigned)ps * 2048u;      // own-layer h[t-1] slot
            // ---- batch-issue ALL remote pulls (one latency exposure, MLP<=14)
            ull hv0[3], hv1[3], iv0[4], iv1[4];
#pragma unroll
            for (int jj = 0; jj < 3; jj++) {
                hv0[jj] = ld_cl(hadr[jj] + po);
                hv1[jj] = ld_cl(hadr[jj] + po + 1024u);
            }
            if (layer > 0) {
                const unsigned pi = (unsigned)(t & 1) * 2048u;  // upstream h[t] slot
#pragma unroll
                for (int j = 0; j < 4; j++) {
                    iv0[j] = ld_cl(up_adr[j] + pi);
                    iv1[j] = ld_cl(up_adr[j] + pi + 1024u);
                }
#pragma unroll
                for (int j = 0; j < 4; j++)
#pragma unroll
                    for (int q = 0; q < 8; q++) { ffma2(acc0[q], iv0[j], Wr[q][j]); ffma2(acc1[q], iv1[j], Wr[q][j]); }
            }
#pragma unroll
            for (int jj = 0; jj < 3; jj++)
#pragma unroll
                for (int q = 0; q < 8; q++) { ffma2(acc0[q], hv0[jj], Wr[q][5 + jj]); ffma2(acc1[q], hv1[jj], Wr[q][5 + jj]); }

            // ---- folded tree reduction: 16 shfl, all static register indexing
            float k[8];
            {
                float s0[8], s1[8];
#pragma unroll
                for (int q = 0; q < 8; q++) {
                    s0[q] = lo32(acc0[q]) + hi32(acc0[q]);
                    s1[q] = lo32(acc1[q]) + hi32(acc1[q]);
                }
                const bool b4 = (lane & 16) != 0;
#pragma unroll
                for (int m = 0; m < 8; m++) {
                    const float a = b4 ? s1[m] : s0[m];
                    const float b = b4 ? s0[m] : s1[m];
                    k[m] = a + __shfl_xor_sync(0xffffffffu, b, 16);
                }
            }
            {
                const bool b3 = (lane & 8) != 0;
#pragma unroll
                for (int q = 0; q < 4; q++) {
                    const float a = b3 ? k[q + 4] : k[q];
                    const float b = b3 ? k[q] : k[q + 4];
                    k[q] = a + __shfl_xor_sync(0xffffffffu, b, 8);
                }
            }
            {
                const bool b2 = (lane & 4) != 0;
#pragma unroll
                for (int q = 0; q < 2; q++) {
                    const float a = b2 ? k[q + 2] : k[q];
                    const float b = b2 ? k[q] : k[q + 2];
                    k[q] = a + __shfl_xor_sync(0xffffffffu, b, 4);
                }
            }
            {
                const bool b1 = (lane & 2) != 0;
                const float a = b1 ? k[1] : k[0];
                const float b = b1 ? k[0] : k[1];
                k[0] = a + __shfl_xor_sync(0xffffffffu, b, 2);
            }
            k[0] += __shfl_xor_sync(0xffffffffu, k[0], 1);

            // ---- activation (fast MUFU tanh) + mask; STG out + LOCAL STS
            if (active_lane) {
                float v = fast_tanh(k[0] + bias_v);
                if (t >= len_v) v = 0.0f;
                *outp = v;
                outp += DEPTH * H_DIM;
                *(((t & 1) ? hp1 : hp0)) = v;
            }
        }

        __syncthreads();                        // STS drained; all iteration-i reads done
        if (i <= T && tid < CL_SZ) {
            arrive_mapped((i & 1) ? ab1 : ab0); // release-arrive to rank 'tid'
        }
    }

    // terminal: no CTA exits while peers may still pull/arrive into it
    asm volatile("barrier.cluster.arrive.aligned;" ::: "memory");
    asm volatile("barrier.cluster.wait.aligned;" ::: "memory");
}

extern "C" void kernel_launch(void* const* d_in, const int* in_sizes, int n_in,
                              void* d_out, int out_size) {
    const float* x    = (const float*)d_in[0];
    const int*   seq  = (const int*)  d_in[1];
    const float* W_ih = (const float*)d_in[2];
    const float* W_hh = (const float*)d_in[3];
    const float* bias = (const float*)d_in[4];
    float* out = (float*)d_out;

    const int B = in_sizes[1];                    // 16
    const int T = in_sizes[0] / (B * H_DIM);      // 2048

    cudaFuncSetAttribute(rnn12_kernel,
                         cudaFuncAttributeNonPortableClusterSizeAllowed, 1);

    rnn12_kernel<<<dim3((B / 2) * 4, DEPTH, 1), NTHREADS>>>(x, seq, W_ih, W_hh, bias, out, T);
}

// round 14
// speedup vs baseline: 2.9269x; 1.3248x over previous
#include <cuda_runtime.h>

// Stacked depth-3 tanh RNN — single 12-CTA cluster per batch-pair, systolic
// lockstep, STAGED-PULL exchange. B=16, T=2048, H=256, DEPTH=3.
// Cluster (4,3,1): rank = cid + 4*layer. Iteration i: layer k computes t=i-k.
// R14: remote data is pulled ONCE per CTA (256 threads x <=2 b64) into local
// SMEM (peer h -> hbuf[ps] natural slots; upstream -> in_s[0]), then all
// FFMAs read local SMEM. Cuts DSMEM producer-port traffic 8x (28KB -> 3.5KB
// per iter), which R13's budget identified as the binding ~1300 cyc/iter.

#define H_DIM 256
#define DEPTH 3
#define NTHREADS 256
#define CL_SZ 12

typedef unsigned long long ull;

__device__ __forceinline__ void ffma2(ull& d, ull a, ull b) {
    asm("fma.rn.f32x2 %0, %1, %2, %0;" : "+l"(d) : "l"(a), "l"(b));
}
__device__ __forceinline__ float lo32(ull v) { return __uint_as_float((unsigned)v); }
__device__ __forceinline__ float hi32(ull v) { return __uint_as_float((unsigned)(v >> 32)); }

__device__ __forceinline__ unsigned smem_u32(const void* p) {
    return (unsigned)__cvta_generic_to_shared(p);
}
__device__ __forceinline__ unsigned mapa_addr(unsigned laddr, int rank) {
    unsigned ra;
    asm volatile("mapa.shared::cluster.u32 %0, %1, %2;" : "=r"(ra) : "r"(laddr), "r"(rank));
    return ra;
}
__device__ __forceinline__ void mbar_init(unsigned mb, int cnt) {
    asm volatile("mbarrier.init.shared.b64 [%0], %1;" :: "r"(mb), "r"(cnt) : "memory");
}
__device__ __forceinline__ void mbar_wait(unsigned mb, int parity) {
    asm volatile(
        "{\n\t"
        ".reg .pred P;\n\t"
        "WL_%=:\n\t"
        "mbarrier.try_wait.parity.acquire.cluster.shared::cta.b64 P, [%0], %1, 0x989680;\n\t"
        "@P bra.uni WD_%=;\n\t"
        "bra.uni WL_%=;\n\t"
        "WD_%=:\n\t"
        "}" :: "r"(mb), "r"(parity) : "memory");
}
__device__ __forceinline__ void arrive_mapped(unsigned addr) {
    asm volatile("mbarrier.arrive.release.cluster.shared::cluster.b64 _, [%0];"
                 :: "r"(addr) : "memory");
}
__device__ __forceinline__ ull ld_cl(unsigned addr) {
    ull v;
    asm volatile("ld.shared::cluster.b64 %0, [%1];" : "=l"(v) : "r"(addr) : "memory");
    return v;
}
// fast tanh (numerical adequacy proven by R4/R5 bit-identical experiment)
__device__ __forceinline__ float fast_tanh(float z) {
    const float e = __expf(z + z);
    return 1.0f - __fdividef(2.0f, e + 1.0f);
}

__global__ void __launch_bounds__(NTHREADS, 1) __cluster_dims__(4, 3, 1)
rnn12_kernel(const float* __restrict__ x,
             const int*   __restrict__ seq_lens,
             const float* __restrict__ W_ih,
             const float* __restrict__ W_hh,
             const float* __restrict__ bias,
             float* out,
             int T) {
    __shared__ float in_s[3][2][256];   // layer0: x ring | layers>0: slot 0 = staged input
    __shared__ float hbuf[2][2][256];   // [slot t&1][batch][n]; own slice + staged peers
    __shared__ __align__(8) ull mbar[2];

    const int cid   = blockIdx.x & 3;
    const int p     = blockIdx.x >> 2;
    const int layer = blockIdx.y;

    const int tid  = threadIdx.x;
    const int w    = tid >> 5;
    const int lane = tid & 31;
    const int n_base = cid * 64 + w * 8;

    const unsigned mb0 = smem_u32(&mbar[0]);
    const unsigned mb1 = smem_u32(&mbar[1]);
    if (tid == 0) { mbar_init(mb0, CL_SZ); mbar_init(mb1, CL_SZ); }
    for (int idx = tid; idx < 2 * 2 * 256; idx += NTHREADS) ((float*)hbuf)[idx] = 0.0f;
    __syncthreads();
    asm volatile("barrier.cluster.arrive.aligned;" ::: "memory");
    asm volatile("barrier.cluster.wait.aligned;" ::: "memory");

    unsigned ab0 = 0, ab1 = 0;
    if (tid < CL_SZ) { ab0 = mapa_addr(mb0, tid); ab1 = mapa_addr(mb1, tid); }

    const unsigned hb = smem_u32(&hbuf[0][0][0]);

    // ---- staging assignments (each thread pulls <=2 b64 per iteration)
    // (a) peer h slices: threads 0..191. Peer c=(cid+1+jj)&3 slice -> its
    //     natural position in local hbuf[ps].
    unsigned st_h_rem = 0;              // + ps*2048 per iter
    ull*     st_h_dst = 0;              // + ps*256 (ull) per iter
    if (tid < 192) {
        const int jj = tid / 64;        // 0..2
        const int r  = tid & 63;
        const int bl = r >> 5;
        const int e  = r & 31;          // b64 within 64-neuron slice
        const int c  = (cid + 1 + jj) & 3;
        st_h_rem = mapa_addr(hb, c + 4 * layer) + (unsigned)(bl * 1024 + c * 256 + e * 8);
        st_h_dst = (ull*)hbuf + (bl * 128 + c * 32 + e);
    }
    // (b) upstream input: all 256 threads (layers>0). Chunk j from upstream
    //     rank j -> in_s[0] linear ull index = tid.
    unsigned st_i_rem = 0;              // + (t&1)*2048 per iter
    ull*     st_i_dst = 0;
    if (layer > 0) {
        const int bl  = tid >> 7;
        const int e   = tid & 127;
        const int j   = e >> 5;
        const int w64 = e & 31;
        st_i_rem = mapa_addr(hb, j + 4 * (layer - 1)) + (unsigned)(bl * 1024 + j * 256 + w64 * 8);
        st_i_dst = (ull*)in_s + tid;
    }

    // local h read pointers (chunk c at ull idx ps*256 + bl*128 + c*32 + lane)
    const ull* hloc = (const ull*)hbuf + (cid * 32 + lane);               // own (slot 4)
    const ull* hpk1 = (const ull*)hbuf + (((cid + 1) & 3) * 32 + lane);   // slot 5
    const ull* hpk2 = (const ull*)hbuf + (((cid + 2) & 3) * 32 + lane);   // slot 6
    const ull* hpk3 = (const ull*)hbuf + (((cid + 3) & 3) * 32 + lane);   // slot 7

    // ---- weights: input chunks j=0..3 in slots 0..3; W_hh permuted by cid:
    //      slot 4+jj holds phys chunk (cid+jj)&3 (own chunk always slot 4).
    ull Wr[8][8];
    {
        const float* wih = W_ih + layer * H_DIM * H_DIM;
        const float* whh = W_hh + layer * H_DIM * H_DIM;
#pragma unroll
        for (int i = 0; i < 8; i++) {
            const int n = n_base + i;
#pragma unroll
            for (int j = 0; j < 4; j++)
                Wr[i][j] = *(const ull*)(wih + n * 256 + (j * 32 + lane) * 2);
#pragma unroll
            for (int jj = 0; jj < 4; jj++) {
                const int c = (cid + jj) & 3;
                Wr[i][4 + jj] = *(const ull*)(whh + n * 256 + (c * 32 + lane) * 2);
            }
        }
    }

    // ---- writer lanes: even lanes. batch = lane>>4, neuron m = 4*b3+2*b2+b1.
    const bool active_lane = (lane & 1) == 0;
    float  bias_v = 0.0f;
    int    len_v  = -1;
    float* outp   = out;
    float* hp0 = 0; float* hp1 = 0;
    if (active_lane) {
        const int bl = lane >> 4;
        const int m  = ((lane >> 3) & 1) * 4 + ((lane >> 2) & 1) * 2 + ((lane >> 1) & 1);
        const int nr = n_base + m;
        const int bg = 2 * p + bl;
        bias_v = bias[layer * H_DIM + nr];
        len_v  = seq_lens[bg];
        outp   = out + (((size_t)bg * T) * DEPTH + layer) * H_DIM + nr;
        hp0 = &hbuf[0][bl][nr];
        hp1 = &hbuf[1][bl][nr];
    }

    // ---- layer-0 x loaders (tid<128): LDG issued 1 iteration before commit
    const bool loader = (layer == 0) && (tid < 128);
    const float* in_ptr = 0;
    int s_bl = 0, s_c4 = 0;
    if (loader) {
        s_bl = tid >> 6;
        s_c4 = (tid & 63) << 2;
        in_ptr = x + ((size_t)(2 * p + s_bl) * T) * H_DIM + s_c4;
        *(float4*)&in_s[0][s_bl][s_c4] = *(const float4*)in_ptr;           // t=0
        *(float4*)&in_s[1][s_bl][s_c4] = *(const float4*)(in_ptr + H_DIM); // t=1
        in_ptr += 2 * H_DIM;                    // -> x[2]
    }
    float4 pf_cur = make_float4(0.f, 0.f, 0.f, 0.f);
    __syncthreads();

    for (int i = 0; i <= T + 1; i++) {
        const int t = i - layer;
        const bool active = (t >= 0) && (t < T);
        const int ps = (t + 1) & 1;             // slot holding h[t-1]
        const unsigned po = (unsigned)ps * 2048u;

        ull acc0[8], acc1[8];
#pragma unroll
        for (int q = 0; q < 8; q++) { acc0[q] = 0ull; acc1[q] = 0ull; }

        // ---- pre-wait (local): issue x[i+2] LDG; own-chunk h FFMA;
        //      layer-0 input FFMA from the ring
        float4 pf_next;
        const bool do_issue = loader && (i + 2 < T);
        if (do_issue) {
            pf_next = *(const float4*)in_ptr;   // x[i+2]
            in_ptr += H_DIM;                    // advance at ISSUE
        }
        if (active) {
            const ull o0 = hloc[ps * 256];
            const ull o1 = hloc[ps * 256 + 128];
#pragma unroll
            for (int q = 0; q < 8; q++) { ffma2(acc0[q], o0, Wr[q][4]); ffma2(acc1[q], o1, Wr[q][4]); }
            if (layer == 0) {
                const ull* i0 = (const ull*)in_s[i % 3][0];
                const ull* i1 = (const ull*)in_s[i % 3][1];
#pragma unroll
                for (int j = 0; j < 4; j++) {
                    const ull a0 = i0[j * 32 + lane];
                    const ull a1 = i1[j * 32 + lane];
#pragma unroll
                    for (int q = 0; q < 8; q++) { ffma2(acc0[q], a0, Wr[q][j]); ffma2(acc1[q], a1, Wr[q][j]); }
                }
            }
        }

        // ---- lockstep wait for iteration i-1 (ping-pong, phase-borrow immune)
        if (i > 0) {
            const int sel = (i - 1) & 1;
            const int par = ((i - 1) >> 1) & 1;
            mbar_wait(sel ? mb1 : mb0, par);
        }

        // ---- commit x[i+1] (issued LAST iteration) into ring slot (i+1)%3
        if (loader && i >= 1 && i + 1 < T) {
            *(float4*)&in_s[(i + 1) % 3][s_bl][s_c4] = pf_cur;
        }
        if (do_issue) pf_cur = pf_next;

        // ---- STAGE: pull each remote datum ONCE into local SMEM
        if (active) {
            if (tid < 192) st_h_dst[ps * 256] = ld_cl(st_h_rem + po);
            if (layer > 0) *st_i_dst = ld_cl(st_i_rem + (unsigned)(t & 1) * 2048u);
        }
        __syncthreads();                        // staged data visible CTA-wide

        if (active) {
            // ---- all FFMAs from LOCAL SMEM
            if (layer > 0) {
                const ull* i0 = (const ull*)in_s[0][0];
                const ull* i1 = (const ull*)in_s[0][1];
#pragma unroll
                for (int j = 0; j < 4; j++) {
                    const ull a0 = i0[j * 32 + lane];
                    const ull a1 = i1[j * 32 + lane];
#pragma unroll
                    for (int q = 0; q < 8; q++) { ffma2(acc0[q], a0, Wr[q][j]); ffma2(acc1[q], a1, Wr[q][j]); }
                }
            }
            {
                const ull h10 = hpk1[ps * 256], h11 = hpk1[ps * 256 + 128];
                const ull h20 = hpk2[ps * 256], h21 = hpk2[ps * 256 + 128];
                const ull h30 = hpk3[ps * 256], h31 = hpk3[ps * 256 + 128];
#pragma unroll
                for (int q = 0; q < 8; q++) {
                    ffma2(acc0[q], h10, Wr[q][5]); ffma2(acc1[q], h11, Wr[q][5]);
                    ffma2(acc0[q], h20, Wr[q][6]); ffma2(acc1[q], h21, Wr[q][6]);
                    ffma2(acc0[q], h30, Wr[q][7]); ffma2(acc1[q], h31, Wr[q][7]);
                }
            }

            // ---- folded tree reduction: 16 shfl, all static register indexing
            float k[8];
            {
                float s0[8], s1[8];
#pragma unroll
                for (int q = 0; q < 8; q++) {
                    s0[q] = lo32(acc0[q]) + hi32(acc0[q]);
                    s1[q] = lo32(acc1[q]) + hi32(acc1[q]);
                }
                const bool b4 = (lane & 16) != 0;
#pragma unroll
                for (int m = 0; m < 8; m++) {
                    const float a = b4 ? s1[m] : s0[m];
                    const float b = b4 ? s0[m] : s1[m];
                    k[m] = a + __shfl_xor_sync(0xffffffffu, b, 16);
                }
            }
            {
                const bool b3 = (lane & 8) != 0;
#pragma unroll
                for (int q = 0; q < 4; q++) {
                    const float a = b3 ? k[q + 4] : k[q];
                    const float b = b3 ? k[q] : k[q + 4];
                    k[q] = a + __shfl_xor_sync(0xffffffffu, b, 8);
                }
            }
            {
                const bool b2 = (lane & 4) != 0;
#pragma unroll
                for (int q = 0; q < 2; q++) {
                    const float a = b2 ? k[q + 2] : k[q];
                    const float b = b2 ? k[q] : k[q + 2];
                    k[q] = a + __shfl_xor_sync(0xffffffffu, b, 4);
                }
            }
            {
                const bool b1 = (lane & 2) != 0;
                const float a = b1 ? k[1] : k[0];
                const float b = b1 ? k[0] : k[1];
                k[0] = a + __shfl_xor_sync(0xffffffffu, b, 2);
            }
            k[0] += __shfl_xor_sync(0xffffffffu, k[0], 1);

            // ---- activation + mask; STG out + LOCAL STS of own h slice
            if (active_lane) {
                float v = fast_tanh(k[0] + bias_v);
                if (t >= len_v) v = 0.0f;
                *outp = v;
                outp += DEPTH * H_DIM;
                *(((t & 1) ? hp1 : hp0)) = v;
            }
        }

        __syncthreads();                        // STS drained; all iteration-i reads done
        if (i <= T && tid < CL_SZ) {
            arrive_mapped((i & 1) ? ab1 : ab0); // release-arrive to rank 'tid'
        }
    }

    // terminal: no CTA exits while peers may still pull/arrive into it
    asm volatile("barrier.cluster.arrive.aligned;" ::: "memory");
    asm volatile("barrier.cluster.wait.aligned;" ::: "memory");
}

extern "C" void kernel_launch(void* const* d_in, const int* in_sizes, int n_in,
                              void* d_out, int out_size) {
    const float* x    = (const float*)d_in[0];
    const int*   seq  = (const int*)  d_in[1];
    const float* W_ih = (const float*)d_in[2];
    const float* W_hh = (const float*)d_in[3];
    const float* bias = (const float*)d_in[4];
    float* out = (float*)d_out;

    const int B = in_sizes[1];                    // 16
    const int T = in_sizes[0] / (B * H_DIM);      // 2048

    cudaFuncSetAttribute(rnn12_kernel,
                         cudaFuncAttributeNonPortableClusterSizeAllowed, 1);

    rnn12_kernel<<<dim3((B / 2) * 4, DEPTH, 1), NTHREADS>>>(x, seq, W_ih, W_hh, bias, out, T);
}

// round 15
// speedup vs baseline: 3.2588x; 1.1134x over previous
#include <cuda_runtime.h>

// Stacked depth-3 tanh RNN — single 12-CTA cluster per batch-pair, systolic
// lockstep, ST.ASYNC PUSH exchange. B=16, T=2048, H=256, DEPTH=3.
// Cluster (4,3,1): rank = cid + 4*layer. Iteration i: layer k computes t=i-k.
// Producers push h (3 own-layer peers) and output (4 downstream CTAs) with
// st.async.mbarrier::complete_tx — the receiver's ping-pong barrier cannot
// flip before the data is physically visible (HW tx accounting), so there is
// ONE fabric traversal on the critical path and no fences. Phase i barrier:
// 13 arrivals (12 lockstep + 1 self arrive.expect_tx) + exact tx bytes.

#define H_DIM 256
#define DEPTH 3
#define NTHREADS 256
#define CL_SZ 12
#define MB_COUNT 13

typedef unsigned long long ull;

__device__ __forceinline__ void ffma2(ull& d, ull a, ull b) {
    asm("fma.rn.f32x2 %0, %1, %2, %0;" : "+l"(d) : "l"(a), "l"(b));
}
__device__ __forceinline__ float lo32(ull v) { return __uint_as_float((unsigned)v); }
__device__ __forceinline__ float hi32(ull v) { return __uint_as_float((unsigned)(v >> 32)); }

__device__ __forceinline__ unsigned smem_u32(const void* p) {
    return (unsigned)__cvta_generic_to_shared(p);
}
__device__ __forceinline__ unsigned mapa_addr(unsigned laddr, int rank) {
    unsigned ra;
    asm volatile("mapa.shared::cluster.u32 %0, %1, %2;" : "=r"(ra) : "r"(laddr), "r"(rank));
    return ra;
}
__device__ __forceinline__ void mbar_init(unsigned mb, int cnt) {
    asm volatile("mbarrier.init.shared.b64 [%0], %1;" :: "r"(mb), "r"(cnt) : "memory");
}
__device__ __forceinline__ void mbar_wait(unsigned mb, int parity) {
    asm volatile(
        "{\n\t"
        ".reg .pred P;\n\t"
        "WL_%=:\n\t"
        "mbarrier.try_wait.parity.acquire.cluster.shared::cta.b64 P, [%0], %1, 0x989680;\n\t"
        "@P bra.uni WD_%=;\n\t"
        "bra.uni WL_%=;\n\t"
        "WD_%=:\n\t"
        "}" :: "r"(mb), "r"(parity) : "memory");
}
__device__ __forceinline__ void arrive_mapped(unsigned addr) {
    asm volatile("mbarrier.arrive.release.cluster.shared::cluster.b64 _, [%0];"
                 :: "r"(addr) : "memory");
}
__device__ __forceinline__ void mbar_expect_arrive(unsigned mb, unsigned bytes) {
    asm volatile("mbarrier.arrive.expect_tx.shared.b64 _, [%0], %1;"
                 :: "r"(mb), "r"(bytes) : "memory");
}
__device__ __forceinline__ void mbar_arrive_local(unsigned mb) {
    asm volatile("mbarrier.arrive.shared.b64 _, [%0];" :: "r"(mb) : "memory");
}
// remote store + tx credit to the mbarrier co-located with the data
__device__ __forceinline__ void st_async_f32(unsigned dst, float v, unsigned mbar) {
    asm volatile("st.async.shared::cluster.mbarrier::complete_tx::bytes.b32 [%0], %1, [%2];"
                 :: "r"(dst), "r"(__float_as_uint(v)), "r"(mbar) : "memory");
}
// fast tanh (numerical adequacy proven by R4/R5 bit-identical experiment)
__device__ __forceinline__ float fast_tanh(float z) {
    const float e = __expf(z + z);
    return 1.0f - __fdividef(2.0f, e + 1.0f);
}

__global__ void __launch_bounds__(NTHREADS, 1) __cluster_dims__(4, 3, 1)
rnn12_kernel(const float* __restrict__ x,
             const int*   __restrict__ seq_lens,
             const float* __restrict__ W_ih,
             const float* __restrict__ W_hh,
             const float* __restrict__ bias,
             float* out,
             int T) {
    __shared__ float in_s[3][2][256];   // layer-0 x ring (local)
    __shared__ float hrecv[2][2][256];  // [slot t&1][batch][n]: own STS + peer pushes
    __shared__ float irecv[2][2][256];  // [slot][batch][n]: upstream output pushes
    __shared__ __align__(8) ull mbar[2];

    const int cid   = blockIdx.x & 3;
    const int p     = blockIdx.x >> 2;
    const int layer = blockIdx.y;

    const int tid  = threadIdx.x;
    const int w    = tid >> 5;
    const int lane = tid & 31;
    const int n_base = cid * 64 + w * 8;

    const unsigned mb0 = smem_u32(&mbar[0]);
    if (tid == 0) { mbar_init(mb0, MB_COUNT); mbar_init(mb0 + 8, MB_COUNT); }
    for (int idx = tid; idx < 2 * 2 * 256; idx += NTHREADS) {
        ((float*)hrecv)[idx] = 0.0f;
        ((float*)irecv)[idx] = 0.0f;
    }
    __syncthreads();
    asm volatile("barrier.cluster.arrive.aligned;" ::: "memory");
    asm volatile("barrier.cluster.wait.aligned;" ::: "memory");

    // lockstep arrive targets (lanes 0..11 -> one rank each); +8 selects mb[1]
    unsigned ab = 0;
    if (tid < CL_SZ) ab = mapa_addr(mb0, tid);

    const unsigned hrb = smem_u32(&hrecv[0][0][0]);
    const unsigned irb = smem_u32(&irecv[0][0][0]);

    // ---- weights: input chunks j=0..3 in slots 0..3; W_hh permuted by cid:
    //      slot 4+jj holds phys chunk (cid+jj)&3 (own chunk always slot 4).
    ull Wr[8][8];
    {
        const float* wih = W_ih + layer * H_DIM * H_DIM;
        const float* whh = W_hh + layer * H_DIM * H_DIM;
#pragma unroll
        for (int i = 0; i < 8; i++) {
            const int n = n_base + i;
#pragma unroll
            for (int j = 0; j < 4; j++)
                Wr[i][j] = *(const ull*)(wih + n * 256 + (j * 32 + lane) * 2);
#pragma unroll
            for (int jj = 0; jj < 4; jj++) {
                const int c = (cid + jj) & 3;
                Wr[i][4 + jj] = *(const ull*)(whh + n * 256 + (c * 32 + lane) * 2);
            }
        }
    }

    // local h read pointers (chunk c at ull idx slot*256 + bl*128 + c*32 + lane)
    const ull* hloc = (const ull*)hrecv + (cid * 32 + lane);               // own
    const ull* hpk1 = (const ull*)hrecv + (((cid + 1) & 3) * 32 + lane);
    const ull* hpk2 = (const ull*)hrecv + (((cid + 2) & 3) * 32 + lane);
    const ull* hpk3 = (const ull*)hrecv + (((cid + 3) & 3) * 32 + lane);
    const ull* iloc = (const ull*)irecv + lane;                            // + j*32

    // ---- writer lanes: even lanes. batch = lane>>4, neuron m = 4*b3+2*b2+b1.
    const bool active_lane = (lane & 1) == 0;
    float  bias_v = 0.0f;
    int    len_v  = -1;
    float* outp   = out;
    float* hown   = 0;                           // local hrecv slot-0 addr (own value)
    unsigned hpd[3], hpm[3];                     // h push: data base (slot0) + mb0
    unsigned ipd[4], ipm[4];                     // downstream push
    if (active_lane) {
        const int bl = lane >> 4;
        const int m  = ((lane >> 3) & 1) * 4 + ((lane >> 2) & 1) * 2 + ((lane >> 1) & 1);
        const int nr = n_base + m;
        const int bg = 2 * p + bl;
        bias_v = bias[layer * H_DIM + nr];
        len_v  = seq_lens[bg];
        outp   = out + (((size_t)bg * T) * DEPTH + layer) * H_DIM + nr;
        hown   = &hrecv[0][bl][nr];
        const unsigned off = (unsigned)(bl * 1024 + nr * 4);
#pragma unroll
        for (int jj = 0; jj < 3; jj++) {
            const int r = ((cid + 1 + jj) & 3) + 4 * layer;
            hpd[jj] = mapa_addr(hrb, r) + off;
            hpm[jj] = mapa_addr(mb0, r);
        }
        if (layer < DEPTH - 1) {
#pragma unroll
            for (int q = 0; q < 4; q++) {
                const int r = q + 4 * (layer + 1);
                ipd[q] = mapa_addr(irb, r) + off;
                ipm[q] = mapa_addr(mb0, r);
            }
        }
    }

    // ---- layer-0 x loaders (tid<128): LDG issued 1 iteration before commit
    const bool loader = (layer == 0) && (tid < 128);
    const float* in_ptr = 0;
    int s_bl = 0, s_c4 = 0;
    if (loader) {
        s_bl = tid >> 6;
        s_c4 = (tid & 63) << 2;
        in_ptr = x + ((size_t)(2 * p + s_bl) * T) * H_DIM + s_c4;
        *(float4*)&in_s[0][s_bl][s_c4] = *(const float4*)in_ptr;           // t=0
        *(float4*)&in_s[1][s_bl][s_c4] = *(const float4*)(in_ptr + H_DIM); // t=1
        in_ptr += 2 * H_DIM;                    // -> x[2]
    }
    float4 pf_cur = make_float4(0.f, 0.f, 0.f, 0.f);
    __syncthreads();

    for (int i = 0; i <= T + 1; i++) {
        const int t = i - layer;
        const bool active = (t >= 0) && (t < T);
        const int ps = (t + 1) & 1;             // slot holding h[t-1]

        ull acc0[8], acc1[8];
#pragma unroll
        for (int q = 0; q < 8; q++) { acc0[q] = 0ull; acc1[q] = 0ull; }

        // ---- pre-wait (local): issue x[i+2] LDG; own-chunk h FFMA (own slice
        //      written by own STS last iteration, ordered by bar.sync);
        //      layer-0 input FFMA from the ring
        float4 pf_next;
        const bool do_issue = loader && (i + 2 < T);
        if (do_issue) {
            pf_next = *(const float4*)in_ptr;   // x[i+2]
            in_ptr += H_DIM;                    // advance at ISSUE
        }
        if (active) {
            const ull o0 = hloc[ps * 256];
            const ull o1 = hloc[ps * 256 + 128];
#pragma unroll
            for (int q = 0; q < 8; q++) { ffma2(acc0[q], o0, Wr[q][4]); ffma2(acc1[q], o1, Wr[q][4]); }
            if (layer == 0) {
                const ull* i0 = (const ull*)in_s[i % 3][0];
                const ull* i1 = (const ull*)in_s[i % 3][1];
#pragma unroll
                for (int j = 0; j < 4; j++) {
                    const ull a0 = i0[j * 32 + lane];
                    const ull a1 = i1[j * 32 + lane];
#pragma unroll
                    for (int q = 0; q < 8; q++) { ffma2(acc0[q], a0, Wr[q][j]); ffma2(acc1[q], a1, Wr[q][j]); }
                }
            }
        }

        // ---- lockstep wait for phase i-1 (ping-pong; tx-gated => data local)
        if (i > 0) {
            const int sel = (i - 1) & 1;
            const int par = ((i - 1) >> 1) & 1;
            mbar_wait(mb0 + 8u * sel, par);
        }

        // ---- self expect-arrive for phase i (1 of the 13 arrivals).
        //      tx bytes derived from producer activity rules (see header).
        if (i <= T && tid == 0) {
            unsigned e = 0;
            if (t >= 0 && t <= T - 2) e += 1536u;                 // 3 peers x 512B
            if (layer > 0 && (t + 1) >= 0 && (t + 1) <= T - 1) e += 2048u; // upstream
            const unsigned mbi = mb0 + 8u * (unsigned)(i & 1);
            if (e) mbar_expect_arrive(mbi, e); else mbar_arrive_local(mbi);
        }

        // ---- commit x[i+1] (issued LAST iteration) into ring slot (i+1)%3
        if (loader && i >= 1 && i + 1 < T) {
            *(float4*)&in_s[(i + 1) % 3][s_bl][s_c4] = pf_cur;
        }
        if (do_issue) pf_cur = pf_next;

        if (active) {
            // ---- all inputs are LOCAL now (pushed during phase i-1)
            if (layer > 0) {
                const unsigned ibase = (unsigned)(t & 1) * 256u;
#pragma unroll
                for (int j = 0; j < 4; j++) {
                    const ull a0 = iloc[ibase + j * 32];
                    const ull a1 = iloc[ibase + 128 + j * 32];
#pragma unroll
                    for (int q = 0; q < 8; q++) { ffma2(acc0[q], a0, Wr[q][j]); ffma2(acc1[q], a1, Wr[q][j]); }
                }
            }
            {
                const ull h10 = hpk1[ps * 256], h11 = hpk1[ps * 256 + 128];
                const ull h20 = hpk2[ps * 256], h21 = hpk2[ps * 256 + 128];
                const ull h30 = hpk3[ps * 256], h31 = hpk3[ps * 256 + 128];
#pragma unroll
                for (int q = 0; q < 8; q++) {
                    ffma2(acc0[q], h10, Wr[q][5]); ffma2(acc1[q], h11, Wr[q][5]);
                    ffma2(acc0[q], h20, Wr[q][6]); ffma2(acc1[q], h21, Wr[q][6]);
                    ffma2(acc0[q], h30, Wr[q][7]); ffma2(acc1[q], h31, Wr[q][7]);
                }
            }

            // ---- folded tree reduction: 16 shfl, all static register indexing
            float k[8];
            {
                float s0[8], s1[8];
#pragma unroll
                for (int q = 0; q < 8; q++) {
                    s0[q] = lo32(acc0[q]) + hi32(acc0[q]);
                    s1[q] = lo32(acc1[q]) + hi32(acc1[q]);
                }
                const bool b4 = (lane & 16) != 0;
#pragma unroll
                for (int m = 0; m < 8; m++) {
                    const float a = b4 ? s1[m] : s0[m];
                    const float b = b4 ? s0[m] : s1[m];
                    k[m] = a + __shfl_xor_sync(0xffffffffu, b, 16);
                }
            }
            {
                const bool b3 = (lane & 8) != 0;
#pragma unroll
                for (int q = 0; q < 4; q++) {
                    const float a = b3 ? k[q + 4] : k[q];
                    const float b = b3 ? k[q] : k[q + 4];
                    k[q] = a + __shfl_xor_sync(0xffffffffu, b, 8);
                }
            }
            {
                const bool b2 = (lane & 4) != 0;
#pragma unroll
                for (int q = 0; q < 2; q++) {
                    const float a = b2 ? k[q + 2] : k[q];
                    const float b = b2 ? k[q] : k[q + 2];
                    k[q] = a + __shfl_xor_sync(0xffffffffu, b, 4);
                }
            }
            {
                const bool b1 = (lane & 2) != 0;
                const float a = b1 ? k[1] : k[0];
                const float b = b1 ? k[0] : k[1];
                k[0] = a + __shfl_xor_sync(0xffffffffu, b, 2);
            }
            k[0] += __shfl_xor_sync(0xffffffffu, k[0], 1);

            // ---- activation + mask; STG out + local STS (own h) + st.async pushes
            if (active_lane) {
                float v = fast_tanh(k[0] + bias_v);
                if (t >= len_v) v = 0.0f;
                *outp = v;
                outp += DEPTH * H_DIM;
                const unsigned so = (unsigned)(t & 1) * 2048u;   // data slot offset
                const unsigned ms = 8u * (unsigned)(i & 1);      // phase-i barrier sel
                hown[(t & 1) * 512] = v;                         // own slice, local STS
                if (t <= T - 2) {
#pragma unroll
                    for (int jj = 0; jj < 3; jj++) st_async_f32(hpd[jj] + so, v, hpm[jj] + ms);
                }
                if (layer < DEPTH - 1) {
#pragma unroll
                    for (int q = 0; q < 4; q++) st_async_f32(ipd[q] + so, v, ipm[q] + ms);
                }
            }
        }

        __syncthreads();                        // own STS drained; all reads done
        if (i <= T && tid < CL_SZ) {
            arrive_mapped(ab + 8u * (unsigned)(i & 1));   // lockstep arrive, phase i
        }
    }

    // terminal: no CTA exits while peers may still push/arrive into it
    asm volatile("barrier.cluster.arrive.aligned;" ::: "memory");
    asm volatile("barrier.cluster.wait.aligned;" ::: "memory");
}

extern "C" void kernel_launch(void* const* d_in, const int* in_sizes, int n_in,
                              void* d_out, int out_size) {
    const float* x    = (const float*)d_in[0];
    const int*   seq  = (const int*)  d_in[1];
    const float* W_ih = (const float*)d_in[2];
    const float* W_hh = (const float*)d_in[3];
    const float* bias = (const float*)d_in[4];
    float* out = (float*)d_out;

    const int B = in_sizes[1];                    // 16
    const int T = in_sizes[0] / (B * H_DIM);      // 2048

    cudaFuncSetAttribute(rnn12_kernel,
                         cudaFuncAttributeNonPortableClusterSizeAllowed, 1);

    rnn12_kernel<<<dim3((B / 2) * 4, DEPTH, 1), NTHREADS>>>(x, seq, W_ih, W_hh, bias, out, T);
}